// round 8
// baseline (speedup 1.0000x reference)
#include <cuda_runtime.h>
#include <cuda_bf16.h>
#include <cstdint>

#define NCELL 65536
#define TST   365

// smem byte offsets
#define HHI 0          // h_hi: 128 rows x 144B (64 bf16 + pad)   = 18432
#define HLO 18432      // h_lo: same                               = 18432
#define XB  36864      // x block: 128 rows x 48B                  =  6144
#define PT  43008      // pt double buffer: 2 x 128 x float2       =  2048
#define YPT 45056      // y partials: 8 x 128 x f32                =  4096
#define SMB 49152

typedef unsigned int u32;
typedef unsigned short u16;

static __device__ __forceinline__ u32 s2u(const void* p) {
    u32 a;
    asm("{ .reg .u64 t; cvta.to.shared.u64 t, %1; cvt.u32.u64 %0, t; }"
        : "=r"(a) : "l"(p));
    return a;
}
static __device__ __forceinline__ float bf2f(u16 b) {
    return __uint_as_float(((u32)b) << 16);
}
static __device__ __forceinline__ u16 f2bf(float f) {
    return __bfloat16_as_ushort(__float2bfloat16(f));
}
static __device__ __forceinline__ u32 pk(u16 a, u16 b) {
    return (u32)a | ((u32)b << 16);
}
static __device__ __forceinline__ float sigm(float x) {
    float e = __expf(-x);
    float r;
    asm("rcp.approx.f32 %0, %1;" : "=f"(r) : "f"(1.0f + e));
    return r;
}
static __device__ __forceinline__ float tanhv(float x) {
    return fmaf(2.0f, sigm(2.0f * x), -1.0f);
}

#define LDSM4(R, ad) \
    asm volatile("ldmatrix.sync.aligned.m8n8.x4.shared.b16 {%0,%1,%2,%3}, [%4];" \
        : "=r"((R)[0]), "=r"((R)[1]), "=r"((R)[2]), "=r"((R)[3]) : "r"(ad) : "memory")

#define HMMA(D, A, B0, B1) \
    asm("mma.sync.aligned.m16n8k16.row.col.f32.bf16.bf16.f32 " \
        "{%0,%1,%2,%3}, {%4,%5,%6,%7}, {%8,%9}, {%0,%1,%2,%3};" \
        : "+f"((D)[0]), "+f"((D)[1]), "+f"((D)[2]), "+f"((D)[3]) \
        : "r"((A)[0]), "r"((A)[1]), "r"((A)[2]), "r"((A)[3]), "r"(B0), "r"(B1))

__global__ void __launch_bounds__(256, 1)
gru_mma_kernel(const float* __restrict__ precip, const float* __restrict__ temp,
               const float* __restrict__ w_ih, const float* __restrict__ w_hh,
               const float* __restrict__ bias, const float* __restrict__ bias_n,
               const float* __restrict__ out_w, const float* __restrict__ out_b,
               const float* __restrict__ init_h, float* __restrict__ out) {
    extern __shared__ char sm[];
    const u32 sb = s2u(sm);
    u16* hhi16 = (u16*)(sm + HHI);
    u16* hlo16 = (u16*)(sm + HLO);
    float2* ptb = (float2*)(sm + PT);
    float* ypart = (float*)(sm + YPT);

    const int tid  = threadIdx.x;
    const int wid  = tid >> 5;
    const int lane = tid & 31;
    const int g    = lane >> 2;
    const int c4   = lane & 3;
    const int k0   = 8 * wid + 2 * c4;     // this thread's hidden-index pair base
    const int cellbase = blockIdx.x * 128;

    // ---------- resident B fragments (built once from gmem) ----------
    // Bh/Bl[grp][kchunk][rr]: Whh hi/lo; grp 0=r,1=z,2=n. Bx[grp][2]: x-chunk (r,z).
    u32 Bh[3][4][2], Bl[3][4][2], Bx[2][2];
#pragma unroll
    for (int grp = 0; grp < 3; ++grp) {
        const int gate = grp * 64 + 8 * wid + g;   // B col (n) = gate
        const float* wr = w_hh + gate * 64;
#pragma unroll
        for (int c = 0; c < 4; ++c) {
#pragma unroll
            for (int rr = 0; rr < 2; ++rr) {
                int kk = c * 16 + rr * 8 + 2 * c4;
                float w0 = wr[kk], w1 = wr[kk + 1];
                u16 h0 = f2bf(w0), h1 = f2bf(w1);
                Bh[grp][c][rr] = pk(h0, h1);
                Bl[grp][c][rr] = pk(f2bf(w0 - bf2f(h0)), f2bf(w1 - bf2f(h1)));
            }
        }
    }
#pragma unroll
    for (int grp = 0; grp < 2; ++grp) {
        const int gate = grp * 64 + 8 * wid + g;
        float w0 = w_ih[gate * 2], w1 = w_ih[gate * 2 + 1], bb = bias[gate];
        u16 w0h = f2bf(w0), w1h = f2bf(w1), bh = f2bf(bb);
        u32 v;
        if (c4 <= 1)      v = pk(w0h, w1h);                 // k rows 0,1 / 2,3: w_hi
        else if (c4 == 2) v = pk(f2bf(w0 - bf2f(w0h)),      // k rows 4,5: w_lo
                                 f2bf(w1 - bf2f(w1h)));
        else              v = pk(bh, f2bf(bb - bf2f(bh)));  // k rows 6,7: bias hi/lo
        Bx[grp][0] = v;
        Bx[grp][1] = 0;                                     // k rows 8-15 unused
    }

    // exact fp32 scalar constants: candidate-gate x-part, bias_n, out_w
    const float wp0 = w_ih[(128 + k0) * 2],     wt0 = w_ih[(128 + k0) * 2 + 1];
    const float wp1 = w_ih[(128 + k0 + 1) * 2], wt1 = w_ih[(128 + k0 + 1) * 2 + 1];
    const float bb0 = bias[128 + k0], bb1 = bias[128 + k0 + 1];
    const float bn0 = bias_n[k0],     bn1 = bias_n[k0 + 1];
    const float ow0 = out_w[k0],      ow1 = out_w[k0 + 1];
    const float ob  = out_b[0];

    // ---------- init h smem (bf16 split of init_h, all cells) ----------
    for (int idx = tid; idx < 8192; idx += 256) {
        int cl = idx >> 6, k = idx & 63;
        float v = init_h[k];
        u16 hi = f2bf(v);
        hhi16[cl * 72 + k] = hi;
        hlo16[cl * 72 + k] = f2bf(v - bf2f(hi));
    }
    // ---------- init x block (t=0) + pt buffer 0; prefetch t=1 ----------
    float pv = 0.f, tv = 0.f;
    if (tid < 128) {
        float p0 = precip[cellbase + tid], t0 = temp[cellbase + tid];
        u16 ph = f2bf(p0), th = f2bf(t0);
        u16 pl = f2bf(p0 - bf2f(ph)), tl = f2bf(t0 - bf2f(th));
        u32* xr = (u32*)(sm + XB + tid * 48);
        xr[0] = pk(ph, th); xr[1] = pk(pl, tl);
        xr[2] = pk(ph, th); xr[3] = pk(0x3F80, 0x3F80);   // cols 6,7 = 1.0
        xr[4] = 0; xr[5] = 0; xr[6] = 0; xr[7] = 0;       // cols 8-15 = 0
        ptb[tid] = make_float2(p0, t0);
        pv = precip[NCELL + cellbase + tid];
        tv = temp[NCELL + cellbase + tid];
    }
    __syncthreads();

    // ldmatrix per-lane address offsets
    const u32 lmoff = (u32)((lane & 15) * 144 + (lane >> 4) * 16);
    const u32 xlm   = (u32)((lane & 15) * 48  + (lane >> 4) * 16);
    const u32 ahi_b = sb + HHI + lmoff;
    const u32 alo_b = sb + HLO + lmoff;
    const u32 ax_b  = sb + XB  + xlm;

    for (int t = 0; t < TST; ++t) {
        float d[8][3][4];
#pragma unroll
        for (int mt = 0; mt < 8; ++mt)
#pragma unroll
            for (int gr = 0; gr < 3; ++gr)
#pragma unroll
                for (int q = 0; q < 4; ++q) d[mt][gr][q] = 0.f;

        // h_hi chunks: x Whi (main) and x Wlo (weight low bits)
#pragma unroll
        for (int c = 0; c < 4; ++c) {
            u32 a[8][4];
#pragma unroll
            for (int mt = 0; mt < 8; ++mt)
                LDSM4(a[mt], ahi_b + mt * 2304 + c * 32);
#pragma unroll
            for (int mt = 0; mt < 8; ++mt) {
                HMMA(d[mt][0], a[mt], Bh[0][c][0], Bh[0][c][1]);
                HMMA(d[mt][1], a[mt], Bh[1][c][0], Bh[1][c][1]);
                HMMA(d[mt][2], a[mt], Bh[2][c][0], Bh[2][c][1]);
                HMMA(d[mt][0], a[mt], Bl[0][c][0], Bl[0][c][1]);
                HMMA(d[mt][1], a[mt], Bl[1][c][0], Bl[1][c][1]);
                HMMA(d[mt][2], a[mt], Bl[2][c][0], Bl[2][c][1]);
            }
        }
        // h_lo chunks: x Whi
#pragma unroll
        for (int c = 0; c < 4; ++c) {
            u32 a[8][4];
#pragma unroll
            for (int mt = 0; mt < 8; ++mt)
                LDSM4(a[mt], alo_b + mt * 2304 + c * 32);
#pragma unroll
            for (int mt = 0; mt < 8; ++mt) {
                HMMA(d[mt][0], a[mt], Bh[0][c][0], Bh[0][c][1]);
                HMMA(d[mt][1], a[mt], Bh[1][c][0], Bh[1][c][1]);
                HMMA(d[mt][2], a[mt], Bh[2][c][0], Bh[2][c][1]);
            }
        }
        // x chunk (r and z groups only)
#pragma unroll
        for (int mt = 0; mt < 8; ++mt) {
            u32 ax[4];
            LDSM4(ax, ax_b + mt * 768);
            HMMA(d[mt][0], ax, Bx[0][0], Bx[0][1]);
            HMMA(d[mt][1], ax, Bx[1][0], Bx[1][1]);
        }

        __syncthreads();   // #1: all smem reads of h/x for step t complete

        // writers: stage x block + pt for step t+1; prefetch t+2
        if (tid < 128) {
            u16 ph = f2bf(pv), th = f2bf(tv);
            u16 pl = f2bf(pv - bf2f(ph)), tl = f2bf(tv - bf2f(th));
            u32* xr = (u32*)(sm + XB + tid * 48);
            xr[0] = pk(ph, th); xr[1] = pk(pl, tl);
            xr[2] = pk(ph, th); xr[3] = pk(0x3F80, 0x3F80);
            ptb[((t + 1) & 1) * 128 + tid] = make_float2(pv, tv);
            int tn = (t + 2 < TST) ? t + 2 : TST - 1;
            pv = precip[tn * NCELL + cellbase + tid];
            tv = temp[tn * NCELL + cellbase + tid];
        }

        // ---------- epilogue: gates, h update, y partials ----------
        const float2* ptc = ptb + (t & 1) * 128;
#pragma unroll
        for (int mt = 0; mt < 8; ++mt) {
#pragma unroll
            for (int half = 0; half < 2; ++half) {
                const int cell = mt * 16 + g + half * 8;
                float2 xv = ptc[cell];
                u32 hw = *(u32*)&hhi16[cell * 72 + k0];
                u32 lw = *(u32*)&hlo16[cell * 72 + k0];
                float ho0 = bf2f((u16)hw)         + bf2f((u16)lw);
                float ho1 = bf2f((u16)(hw >> 16)) + bf2f((u16)(lw >> 16));
                float Dr0 = d[mt][0][2 * half + 0], Dr1 = d[mt][0][2 * half + 1];
                float Dz0 = d[mt][1][2 * half + 0], Dz1 = d[mt][1][2 * half + 1];
                float Dn0 = d[mt][2][2 * half + 0], Dn1 = d[mt][2][2 * half + 1];
                float r0 = sigm(Dr0), r1 = sigm(Dr1);
                float z0 = sigm(Dz0), z1 = sigm(Dz1);
                float in0 = fmaf(wp0, xv.x, fmaf(wt0, xv.y, bb0));
                float in1 = fmaf(wp1, xv.x, fmaf(wt1, xv.y, bb1));
                float n0 = tanhv(fmaf(r0, Dn0 + bn0, in0));
                float n1 = tanhv(fmaf(r1, Dn1 + bn1, in1));
                float h0 = fmaf(z0, ho0 - n0, n0);   // new + z*(h_old - new)
                float h1 = fmaf(z1, ho1 - n1, n1);
                u16 h0h = f2bf(h0), h1h = f2bf(h1);
                *(u32*)&hhi16[cell * 72 + k0] = pk(h0h, h1h);
                *(u32*)&hlo16[cell * 72 + k0] =
                    pk(f2bf(h0 - bf2f(h0h)), f2bf(h1 - bf2f(h1h)));
                float yq = fmaf(ow0, h0, ow1 * h1);
                yq += __shfl_xor_sync(0xffffffffu, yq, 1);
                yq += __shfl_xor_sync(0xffffffffu, yq, 2);
                if (c4 == 0) ypart[wid * 128 + cell] = yq;
            }
        }
        __syncthreads();   // #2: h/x/ypart writes visible

        if (tid < 128) {
            float y = ob;
#pragma unroll
            for (int w = 0; w < 8; ++w) y += ypart[w * 128 + tid];
            out[t * NCELL + cellbase + tid] = y;
        }
    }

    // ---------- final hidden state ----------
    for (int idx = tid; idx < 8192; idx += 256) {
        int cl = idx >> 6, k = idx & 63;
        float v = bf2f(hhi16[cl * 72 + k]) + bf2f(hlo16[cl * 72 + k]);
        out[(long long)TST * NCELL + (long long)(cellbase + cl) * 64 + k] = v;
    }
}

extern "C" void kernel_launch(void* const* d_in, const int* in_sizes, int n_in,
                              void* d_out, int out_size) {
    const float* precip = (const float*)d_in[0];
    const float* temp   = (const float*)d_in[1];
    const float* w_ih   = (const float*)d_in[2];
    const float* w_hh   = (const float*)d_in[3];
    const float* bias   = (const float*)d_in[4];
    const float* bias_n = (const float*)d_in[5];
    const float* out_w  = (const float*)d_in[6];
    const float* out_b  = (const float*)d_in[7];
    const float* init_h = (const float*)d_in[8];
    float* out = (float*)d_out;

    cudaFuncSetAttribute(gru_mma_kernel,
                         cudaFuncAttributeMaxDynamicSharedMemorySize, SMB);
    gru_mma_kernel<<<NCELL / 128, 256, SMB>>>(
        precip, temp, w_ih, w_hh, bias, bias_n, out_w, out_b, init_h, out);
}

// round 9
// speedup vs baseline: 2.0935x; 2.0935x over previous
#include <cuda_runtime.h>
#include <cuda_fp16.h>
#include <cstdint>

#define NCELL 65536
#define TST   365
#define CPB   64
#define NBLK  (NCELL / CPB)

// smem byte offsets
#define H16   0        // h f16 tile: 64 rows x 144B           =  9216
#define X16   9216     // x f16 tile: 64 rows x 16B            =  1024
#define WLO   10240    // W_lo: 24 slots x 256 u32             = 24576
#define PTB   34816    // p,t double buffer: 2 x 64 x float2   =  1024
#define YPT   35840    // y partials: 8 x 64 f32               =  2048
#define SMB   37888

typedef unsigned int u32;
typedef unsigned short u16;

static __device__ __forceinline__ u32 s2u(const void* p) {
    u32 a;
    asm("{ .reg .u64 t; cvta.to.shared.u64 t, %1; cvt.u32.u64 %0, t; }"
        : "=r"(a) : "l"(p));
    return a;
}
static __device__ __forceinline__ u16 f2h(float f) {
    return __half_as_ushort(__float2half(f));
}
static __device__ __forceinline__ u32 pk(u16 a, u16 b) {
    return (u32)a | ((u32)b << 16);
}
static __device__ __forceinline__ float tanha(float x) {   // fast sigmoid core
    float r;
    asm("tanh.approx.f32 %0, %1;" : "=f"(r) : "f"(x));
    return r;
}
static __device__ __forceinline__ float sigm_fast(float x) {
    return fmaf(tanha(0.5f * x), 0.5f, 0.5f);
}
static __device__ __forceinline__ float tanhe(float x) {   // exact-ish tanh
    float e = __expf(-2.0f * x), r;
    asm("rcp.approx.f32 %0, %1;" : "=f"(r) : "f"(1.0f + e));
    return fmaf(2.0f, r, -1.0f);
}

#define LDSM4(R, ad) \
    asm volatile("ldmatrix.sync.aligned.m8n8.x4.shared.b16 {%0,%1,%2,%3}, [%4];" \
        : "=r"((R)[0]), "=r"((R)[1]), "=r"((R)[2]), "=r"((R)[3]) : "r"(ad) : "memory")
#define LDSM2(R, ad) \
    asm volatile("ldmatrix.sync.aligned.m8n8.x2.shared.b16 {%0,%1}, [%2];" \
        : "=r"((R)[0]), "=r"((R)[1]) : "r"(ad) : "memory")
#define HMMA16(D, A, B0, B1) \
    asm("mma.sync.aligned.m16n8k16.row.col.f32.f16.f16.f32 " \
        "{%0,%1,%2,%3}, {%4,%5,%6,%7}, {%8,%9}, {%0,%1,%2,%3};" \
        : "+f"((D)[0]), "+f"((D)[1]), "+f"((D)[2]), "+f"((D)[3]) \
        : "r"((A)[0]), "r"((A)[1]), "r"((A)[2]), "r"((A)[3]), "r"(B0), "r"(B1))
#define HMMA8(D, A, B0) \
    asm("mma.sync.aligned.m16n8k8.row.col.f32.f16.f16.f32 " \
        "{%0,%1,%2,%3}, {%4,%5}, {%6}, {%0,%1,%2,%3};" \
        : "+f"((D)[0]), "+f"((D)[1]), "+f"((D)[2]), "+f"((D)[3]) \
        : "r"((A)[0]), "r"((A)[1]), "r"(B0))

__global__ void __launch_bounds__(256, 2)
gru_f16_kernel(const float* __restrict__ precip, const float* __restrict__ temp,
               const float* __restrict__ w_ih, const float* __restrict__ w_hh,
               const float* __restrict__ bias, const float* __restrict__ bias_n,
               const float* __restrict__ out_w, const float* __restrict__ out_b,
               const float* __restrict__ init_h, float* __restrict__ out) {
    extern __shared__ char sm[];
    const u32 sb = s2u(sm);
    u16*  h16  = (u16*)(sm + H16);
    u32*  wlo  = (u32*)(sm + WLO);
    float2* ptb = (float2*)(sm + PTB);
    float* ypart = (float*)(sm + YPT);

    const int tid  = threadIdx.x;
    const int wid  = tid >> 5;
    const int lane = tid & 31;
    const int g    = lane >> 2;
    const int c4   = lane & 3;
    const int k0   = 8 * wid + 2 * c4;
    const int cellbase = blockIdx.x * CPB;

    // ---- W_hi register fragments (f16 high part of W_hh) ----
    u32 Bh[3][4][2];
#pragma unroll
    for (int grp = 0; grp < 3; ++grp) {
        const float* wr = w_hh + (grp * 64 + 8 * wid + g) * 64;
#pragma unroll
        for (int c = 0; c < 4; ++c)
#pragma unroll
            for (int rr = 0; rr < 2; ++rr) {
                int kk = c * 16 + rr * 8 + 2 * c4;
                Bh[grp][c][rr] = pk(f2h(wr[kk]), f2h(wr[kk + 1]));
            }
    }
    // ---- x-chunk B frags (r,z gates): k rows = (w_p, w_t, bias, 0..) ----
    u32 Bx[2];
#pragma unroll
    for (int grp = 0; grp < 2; ++grp) {
        int gate = grp * 64 + 8 * wid + g;
        u32 v = 0;
        if (c4 == 0)      v = pk(f2h(w_ih[gate * 2]), f2h(w_ih[gate * 2 + 1]));
        else if (c4 == 1) v = pk(f2h(bias[gate]), 0);
        Bx[grp] = v;
    }
    // ---- W_lo into smem: slot = (grp*4+c)*2+rr, word = gate*4 + c4 ----
    for (int idx = tid; idx < 6144; idx += 256) {
        int slot = idx >> 8, rem = idx & 255;
        int gate = rem >> 2, cc4 = rem & 3;
        int grp = slot >> 3, cc = (slot & 7) >> 1, rr = slot & 1;
        int kk = cc * 16 + rr * 8 + 2 * cc4;
        const float* wr = w_hh + (grp * 64 + gate) * 64;
        float w0 = wr[kk], w1 = wr[kk + 1];
        wlo[idx & ~255 | rem] = pk(f2h(w0 - __half2float(__float2half(w0))),
                                   f2h(w1 - __half2float(__float2half(w1))));
    }
    // ---- exact scalars for candidate gate + output ----
    const float wp0 = w_ih[(128 + k0) * 2],     wt0 = w_ih[(128 + k0) * 2 + 1];
    const float wp1 = w_ih[(128 + k0 + 1) * 2], wt1 = w_ih[(128 + k0 + 1) * 2 + 1];
    const float bb0 = bias[128 + k0], bb1 = bias[128 + k0 + 1];
    const float bn0 = bias_n[k0],     bn1 = bias_n[k0 + 1];
    const float ow0 = out_w[k0],      ow1 = out_w[k0 + 1];
    const float ob  = out_b[0];

    // ---- h state: fp32 in regs (thread owns fixed (cell,k) pairs) ----
    float hreg[16];
#pragma unroll
    for (int u = 0; u < 16; ++u) hreg[u] = init_h[k0 + (u & 1)];
    // h f16 tile init
    for (int idx = tid; idx < 64 * 64; idx += 256)
        h16[(idx >> 6) * 72 + (idx & 63)] = f2h(init_h[idx & 63]);
    // x tile (t=0) + pt buffer; prefetch t=1
    float pv = 0.f, tv = 0.f;
    if (tid < CPB) {
        float p0 = precip[cellbase + tid], t0 = temp[cellbase + tid];
        *(uint4*)(sm + X16 + tid * 16) =
            make_uint4(pk(f2h(p0), f2h(t0)), pk(0x3C00, 0), 0, 0);  // 0x3C00 = 1.0h
        ptb[tid] = make_float2(p0, t0);
        pv = precip[NCELL + cellbase + tid];
        tv = temp[NCELL + cellbase + tid];
    }
    __syncthreads();

    const u32 ah_b = sb + H16 + (u32)((lane & 15) * 144 + (lane >> 4) * 16);
    const u32 ax_b = sb + X16 + (u32)((lane & 15) * 16);
    const int wg4 = (8 * wid + g) * 4 + c4;

    for (int t = 0; t < TST; ++t) {
        float d[4][3][4];
#pragma unroll
        for (int mt = 0; mt < 4; ++mt)
#pragma unroll
            for (int gr = 0; gr < 3; ++gr)
#pragma unroll
                for (int q = 0; q < 4; ++q) d[mt][gr][q] = 0.f;

#pragma unroll
        for (int c = 0; c < 4; ++c) {
            u32 a[4][4];
#pragma unroll
            for (int mt = 0; mt < 4; ++mt)
                LDSM4(a[mt], ah_b + mt * 2304 + c * 32);
#pragma unroll
            for (int grp = 0; grp < 3; ++grp) {
                u32 bl0 = wlo[((grp * 4 + c) * 2 + 0) * 256 + wg4];
                u32 bl1 = wlo[((grp * 4 + c) * 2 + 1) * 256 + wg4];
#pragma unroll
                for (int mt = 0; mt < 4; ++mt) {
                    HMMA16(d[mt][grp], a[mt], Bh[grp][c][0], Bh[grp][c][1]);
                    HMMA16(d[mt][grp], a[mt], bl0, bl1);
                }
            }
        }
        // x chunk (adds w_ih·x + bias to r,z pre-activations)
#pragma unroll
        for (int mt = 0; mt < 4; ++mt) {
            u32 ax[2];
            LDSM2(ax, ax_b + mt * 256);
            HMMA8(d[mt][0], ax, Bx[0]);
            HMMA8(d[mt][1], ax, Bx[1]);
        }

        __syncthreads();   // #1: all reads of h16/x16 for step t done

        // stage x for t+1; prefetch t+2
        if (tid < CPB) {
            *(uint4*)(sm + X16 + tid * 16) =
                make_uint4(pk(f2h(pv), f2h(tv)), pk(0x3C00, 0), 0, 0);
            ptb[((t + 1) & 1) * CPB + tid] = make_float2(pv, tv);
            int tn = (t + 2 < TST) ? t + 2 : TST - 1;
            pv = precip[tn * NCELL + cellbase + tid];
            tv = temp[tn * NCELL + cellbase + tid];
        }

        // ---- epilogue ----
        const float2* ptc = ptb + (t & 1) * CPB;
#pragma unroll
        for (int mt = 0; mt < 4; ++mt) {
#pragma unroll
            for (int half = 0; half < 2; ++half) {
                const int cell = mt * 16 + g + half * 8;
                const int u = mt * 4 + half * 2;
                float2 xv = ptc[cell];
                float Dr0 = d[mt][0][2 * half],     Dr1 = d[mt][0][2 * half + 1];
                float Dz0 = d[mt][1][2 * half],     Dz1 = d[mt][1][2 * half + 1];
                float Dn0 = d[mt][2][2 * half],     Dn1 = d[mt][2][2 * half + 1];
                float r0 = sigm_fast(Dr0), r1 = sigm_fast(Dr1);
                float z0 = sigm_fast(Dz0), z1 = sigm_fast(Dz1);
                float ig0 = fmaf(wp0, xv.x, fmaf(wt0, xv.y, bb0));
                float ig1 = fmaf(wp1, xv.x, fmaf(wt1, xv.y, bb1));
                float n0 = tanhe(fmaf(r0, Dn0 + bn0, ig0));
                float n1 = tanhe(fmaf(r1, Dn1 + bn1, ig1));
                float h0 = fmaf(z0, hreg[u] - n0, n0);
                float h1 = fmaf(z1, hreg[u + 1] - n1, n1);
                hreg[u] = h0; hreg[u + 1] = h1;
                *(u32*)&h16[cell * 72 + k0] = pk(f2h(h0), f2h(h1));
                float yq = fmaf(ow0, h0, ow1 * h1);
                yq += __shfl_xor_sync(0xffffffffu, yq, 1);
                yq += __shfl_xor_sync(0xffffffffu, yq, 2);
                if (c4 == 0) ypart[wid * CPB + cell] = yq;
            }
        }
        __syncthreads();   // #2: h16/x16/ypart writes visible

        if (tid < CPB) {
            float y = ob;
#pragma unroll
            for (int w = 0; w < 8; ++w) y += ypart[w * CPB + tid];
            out[t * NCELL + cellbase + tid] = y;
        }
    }

    // ---- final hidden state (exact fp32 from regs) ----
#pragma unroll
    for (int u = 0; u < 16; ++u) {
        int cell = (u >> 2) * 16 + g + ((u >> 1) & 1) * 8;
        int k = k0 + (u & 1);
        out[(long long)TST * NCELL + (long long)(cellbase + cell) * 64 + k] = hreg[u];
    }
}

extern "C" void kernel_launch(void* const* d_in, const int* in_sizes, int n_in,
                              void* d_out, int out_size) {
    const float* precip = (const float*)d_in[0];
    const float* temp   = (const float*)d_in[1];
    const float* w_ih   = (const float*)d_in[2];
    const float* w_hh   = (const float*)d_in[3];
    const float* bias   = (const float*)d_in[4];
    const float* bias_n = (const float*)d_in[5];
    const float* out_w  = (const float*)d_in[6];
    const float* out_b  = (const float*)d_in[7];
    const float* init_h = (const float*)d_in[8];
    float* out = (float*)d_out;

    gru_f16_kernel<<<NBLK, 256, SMB>>>(
        precip, temp, w_ih, w_hh, bias, bias_n, out_w, out_b, init_h, out);
}

// round 10
// speedup vs baseline: 3.1954x; 1.5263x over previous
#include <cuda_runtime.h>
#include <cuda_fp16.h>
#include <cstdint>

#define NCELL 65536
#define TST   365
#define CPB   64
#define NBLK  (NCELL / CPB)

// smem byte offsets
#define H16   0        // h f16 tile: 64 rows x 144B           =  9216
#define X16   9216     // x f16 tile: 64 rows x 16B            =  1024
#define PTB   10240    // p,t double buffer: 2 x 64 x float2   =  1024
#define YPT   11264    // y partials: 8 x 64 f32               =  2048
#define SMB   13312

typedef unsigned int u32;
typedef unsigned short u16;

static __device__ __forceinline__ u32 s2u(const void* p) {
    u32 a;
    asm("{ .reg .u64 t; cvta.to.shared.u64 t, %1; cvt.u32.u64 %0, t; }"
        : "=r"(a) : "l"(p));
    return a;
}
static __device__ __forceinline__ u16 f2h(float f) {
    return __half_as_ushort(__float2half(f));
}
static __device__ __forceinline__ u32 pk(u16 a, u16 b) {
    return (u32)a | ((u32)b << 16);
}
static __device__ __forceinline__ float tanha(float x) {
    float r;
    asm("tanh.approx.f32 %0, %1;" : "=f"(r) : "f"(x));
    return r;
}
static __device__ __forceinline__ float sigm_fast(float x) {
    return fmaf(tanha(0.5f * x), 0.5f, 0.5f);
}

#define LDSM4(R, ad) \
    asm volatile("ldmatrix.sync.aligned.m8n8.x4.shared.b16 {%0,%1,%2,%3}, [%4];" \
        : "=r"((R)[0]), "=r"((R)[1]), "=r"((R)[2]), "=r"((R)[3]) : "r"(ad) : "memory")
#define LDSM2(R, ad) \
    asm volatile("ldmatrix.sync.aligned.m8n8.x2.shared.b16 {%0,%1}, [%2];" \
        : "=r"((R)[0]), "=r"((R)[1]) : "r"(ad) : "memory")
#define HMMA16(D, A, B0, B1) \
    asm("mma.sync.aligned.m16n8k16.row.col.f32.f16.f16.f32 " \
        "{%0,%1,%2,%3}, {%4,%5,%6,%7}, {%8,%9}, {%0,%1,%2,%3};" \
        : "+f"((D)[0]), "+f"((D)[1]), "+f"((D)[2]), "+f"((D)[3]) \
        : "r"((A)[0]), "r"((A)[1]), "r"((A)[2]), "r"((A)[3]), "r"(B0), "r"(B1))
#define HMMA8(D, A, B0) \
    asm("mma.sync.aligned.m16n8k8.row.col.f32.f16.f16.f32 " \
        "{%0,%1,%2,%3}, {%4,%5}, {%6}, {%0,%1,%2,%3};" \
        : "+f"((D)[0]), "+f"((D)[1]), "+f"((D)[2]), "+f"((D)[3]) \
        : "r"((A)[0]), "r"((A)[1]), "r"(B0))

__global__ void __launch_bounds__(256, 2)
gru_f16_kernel(const float* __restrict__ precip, const float* __restrict__ temp,
               const float* __restrict__ w_ih, const float* __restrict__ w_hh,
               const float* __restrict__ bias, const float* __restrict__ bias_n,
               const float* __restrict__ out_w, const float* __restrict__ out_b,
               const float* __restrict__ init_h, float* __restrict__ out) {
    extern __shared__ char sm[];
    const u32 sb = s2u(sm);
    u16*  h16  = (u16*)(sm + H16);
    float2* ptb = (float2*)(sm + PTB);
    float* ypart = (float*)(sm + YPT);

    const int tid  = threadIdx.x;
    const int wid  = tid >> 5;
    const int lane = tid & 31;
    const int g    = lane >> 2;
    const int c4   = lane & 3;
    const int k0   = 8 * wid + 2 * c4;
    const int cellbase = blockIdx.x * CPB;

    // ---- W_hh register fragments (rounded f16) ----
    u32 Bh[3][4][2];
#pragma unroll
    for (int grp = 0; grp < 3; ++grp) {
        const float* wr = w_hh + (grp * 64 + 8 * wid + g) * 64;
#pragma unroll
        for (int c = 0; c < 4; ++c)
#pragma unroll
            for (int rr = 0; rr < 2; ++rr) {
                int kk = c * 16 + rr * 8 + 2 * c4;
                Bh[grp][c][rr] = pk(f2h(wr[kk]), f2h(wr[kk + 1]));
            }
    }
    // ---- x-chunk B frags (r,z gates): k rows = (w_p, w_t, bias, 0..) ----
    u32 Bx[2];
#pragma unroll
    for (int grp = 0; grp < 2; ++grp) {
        int gate = grp * 64 + 8 * wid + g;
        u32 v = 0;
        if (c4 == 0)      v = pk(f2h(w_ih[gate * 2]), f2h(w_ih[gate * 2 + 1]));
        else if (c4 == 1) v = pk(f2h(bias[gate]), 0);
        Bx[grp] = v;
    }
    // ---- exact scalars for candidate gate + output ----
    const float wp0 = w_ih[(128 + k0) * 2],     wt0 = w_ih[(128 + k0) * 2 + 1];
    const float wp1 = w_ih[(128 + k0 + 1) * 2], wt1 = w_ih[(128 + k0 + 1) * 2 + 1];
    const float bb0 = bias[128 + k0], bb1 = bias[128 + k0 + 1];
    const float bn0 = bias_n[k0],     bn1 = bias_n[k0 + 1];
    const float ow0 = out_w[k0],      ow1 = out_w[k0 + 1];
    const float ob  = out_b[0];

    // ---- h state: fp32 in regs (thread owns fixed (cell,k) pairs) ----
    float hreg[16];
#pragma unroll
    for (int u = 0; u < 16; ++u) hreg[u] = init_h[k0 + (u & 1)];
    for (int idx = tid; idx < 64 * 64; idx += 256)
        h16[(idx >> 6) * 72 + (idx & 63)] = f2h(init_h[idx & 63]);
    // x tile (t=0) + pt buffer; prefetch t=1
    float pv = 0.f, tv = 0.f;
    if (tid < CPB) {
        float p0 = precip[cellbase + tid], t0 = temp[cellbase + tid];
        *(uint4*)(sm + X16 + tid * 16) =
            make_uint4(pk(f2h(p0), f2h(t0)), pk(0x3C00, 0), 0, 0);  // 1.0h
        ptb[tid] = make_float2(p0, t0);
        pv = precip[NCELL + cellbase + tid];
        tv = temp[NCELL + cellbase + tid];
    }
    __syncthreads();

    const u32 ah_b = sb + H16 + (u32)((lane & 15) * 144 + (lane >> 4) * 16);
    const u32 ax_b = sb + X16 + (u32)((lane & 15) * 16);

    for (int t = 0; t < TST; ++t) {
        float d[4][3][4];
#pragma unroll
        for (int mt = 0; mt < 4; ++mt)
#pragma unroll
            for (int gr = 0; gr < 3; ++gr)
#pragma unroll
                for (int q = 0; q < 4; ++q) d[mt][gr][q] = 0.f;

#pragma unroll
        for (int c = 0; c < 4; ++c) {
            u32 a[4][4];
#pragma unroll
            for (int mt = 0; mt < 4; ++mt)
                LDSM4(a[mt], ah_b + mt * 2304 + c * 32);
#pragma unroll
            for (int mt = 0; mt < 4; ++mt) {
                HMMA16(d[mt][0], a[mt], Bh[0][c][0], Bh[0][c][1]);
                HMMA16(d[mt][1], a[mt], Bh[1][c][0], Bh[1][c][1]);
                HMMA16(d[mt][2], a[mt], Bh[2][c][0], Bh[2][c][1]);
            }
        }
        // x chunk (adds w_ih·x + bias to r,z pre-activations)
#pragma unroll
        for (int mt = 0; mt < 4; ++mt) {
            u32 ax[2];
            LDSM2(ax, ax_b + mt * 256);
            HMMA8(d[mt][0], ax, Bx[0]);
            HMMA8(d[mt][1], ax, Bx[1]);
        }

        __syncthreads();   // #1: all reads of h16/x16 for step t done

        // stage x for t+1; prefetch t+2
        if (tid < CPB) {
            *(uint4*)(sm + X16 + tid * 16) =
                make_uint4(pk(f2h(pv), f2h(tv)), pk(0x3C00, 0), 0, 0);
            ptb[((t + 1) & 1) * CPB + tid] = make_float2(pv, tv);
            int tn = (t + 2 < TST) ? t + 2 : TST - 1;
            pv = precip[tn * NCELL + cellbase + tid];
            tv = temp[tn * NCELL + cellbase + tid];
        }

        // ---- epilogue ----
        const float2* ptc = ptb + (t & 1) * CPB;
#pragma unroll
        for (int mt = 0; mt < 4; ++mt) {
#pragma unroll
            for (int half = 0; half < 2; ++half) {
                const int cell = mt * 16 + g + half * 8;
                const int u = mt * 4 + half * 2;
                float2 xv = ptc[cell];
                float Dr0 = d[mt][0][2 * half], Dr1 = d[mt][0][2 * half + 1];
                float Dz0 = d[mt][1][2 * half], Dz1 = d[mt][1][2 * half + 1];
                float Dn0 = d[mt][2][2 * half], Dn1 = d[mt][2][2 * half + 1];
                float r0 = sigm_fast(Dr0), r1 = sigm_fast(Dr1);
                float z0 = sigm_fast(Dz0), z1 = sigm_fast(Dz1);
                float ig0 = fmaf(wp0, xv.x, fmaf(wt0, xv.y, bb0));
                float ig1 = fmaf(wp1, xv.x, fmaf(wt1, xv.y, bb1));
                float n0 = tanha(fmaf(r0, Dn0 + bn0, ig0));
                float n1 = tanha(fmaf(r1, Dn1 + bn1, ig1));
                float h0 = fmaf(z0, hreg[u] - n0, n0);
                float h1 = fmaf(z1, hreg[u + 1] - n1, n1);
                hreg[u] = h0; hreg[u + 1] = h1;
                *(u32*)&h16[cell * 72 + k0] = pk(f2h(h0), f2h(h1));
                float yq = fmaf(ow0, h0, ow1 * h1);
                yq += __shfl_xor_sync(0xffffffffu, yq, 1);
                yq += __shfl_xor_sync(0xffffffffu, yq, 2);
                if (c4 == 0) ypart[wid * CPB + cell] = yq;
            }
        }
        __syncthreads();   // #2: h16/x16/ypart writes visible

        if (tid < CPB) {
            float y = ob;
#pragma unroll
            for (int w = 0; w < 8; ++w) y += ypart[w * CPB + tid];
            out[t * NCELL + cellbase + tid] = y;
        }
    }

    // ---- final hidden state (exact fp32 from regs) ----
#pragma unroll
    for (int u = 0; u < 16; ++u) {
        int cell = (u >> 2) * 16 + g + ((u >> 1) & 1) * 8;
        int k = k0 + (u & 1);
        out[(long long)TST * NCELL + (long long)(cellbase + cell) * 64 + k] = hreg[u];
    }
}

extern "C" void kernel_launch(void* const* d_in, const int* in_sizes, int n_in,
                              void* d_out, int out_size) {
    const float* precip = (const float*)d_in[0];
    const float* temp   = (const float*)d_in[1];
    const float* w_ih   = (const float*)d_in[2];
    const float* w_hh   = (const float*)d_in[3];
    const float* bias   = (const float*)d_in[4];
    const float* bias_n = (const float*)d_in[5];
    const float* out_w  = (const float*)d_in[6];
    const float* out_b  = (const float*)d_in[7];
    const float* init_h = (const float*)d_in[8];
    float* out = (float*)d_out;

    gru_f16_kernel<<<NBLK, 256, SMB>>>(
        precip, temp, w_ih, w_hh, bias, bias_n, out_w, out_b, init_h, out);
}

// round 11
// speedup vs baseline: 3.1993x; 1.0012x over previous
#include <cuda_runtime.h>
#include <cuda_fp16.h>
#include <cstdint>

#define NCELL 65536
#define TST   365
#define CPB   64
#define NBLK  (NCELL / CPB)

// smem byte offsets
#define H16   0        // h f16 tile: 64 rows x 144B            = 9216
#define X16   9216     // x f16 tile: 2 bufs x 64 rows x 16B    = 2048
#define PTB   11264    // p,t fp32: 2 bufs x 64 x float2        = 1024
#define YPT   12288    // y partials: 2 bufs x 8 x 64 f32       = 4096
#define SMB   16384

typedef unsigned int u32;
typedef unsigned short u16;

static __device__ __forceinline__ u32 s2u(const void* p) {
    u32 a;
    asm("{ .reg .u64 t; cvta.to.shared.u64 t, %1; cvt.u32.u64 %0, t; }"
        : "=r"(a) : "l"(p));
    return a;
}
static __device__ __forceinline__ u16 f2h(float f) {
    return __half_as_ushort(__float2half(f));
}
static __device__ __forceinline__ u32 pk(u16 a, u16 b) {
    return (u32)a | ((u32)b << 16);
}
static __device__ __forceinline__ float tanha(float x) {
    float r;
    asm("tanh.approx.f32 %0, %1;" : "=f"(r) : "f"(x));
    return r;
}
// packed sigmoid of two fp32 pre-activations via one f16x2 tanh MUFU
static __device__ __forceinline__ float2 sigm2_fast(float x0, float x1) {
    u32 p, s, th;
    asm("cvt.rn.f16x2.f32 %0, %1, %2;" : "=r"(p) : "f"(x1), "f"(x0)); // lo=x0,hi=x1
    asm("mul.f16x2 %0, %1, %2;" : "=r"(s) : "r"(p), "r"(0x38003800u)); // * 0.5
    asm("tanh.approx.f16x2 %0, %1;" : "=r"(th) : "r"(s));
    __half2 h2 = *reinterpret_cast<__half2*>(&th);
    float2 f = __half22float2(h2);
    return make_float2(fmaf(f.x, 0.5f, 0.5f), fmaf(f.y, 0.5f, 0.5f));
}

#define LDSM4(R, ad) \
    asm volatile("ldmatrix.sync.aligned.m8n8.x4.shared.b16 {%0,%1,%2,%3}, [%4];" \
        : "=r"((R)[0]), "=r"((R)[1]), "=r"((R)[2]), "=r"((R)[3]) : "r"(ad) : "memory")
#define LDSM2(R, ad) \
    asm volatile("ldmatrix.sync.aligned.m8n8.x2.shared.b16 {%0,%1}, [%2];" \
        : "=r"((R)[0]), "=r"((R)[1]) : "r"(ad) : "memory")
#define HMMA16(D, A, B0, B1) \
    asm("mma.sync.aligned.m16n8k16.row.col.f32.f16.f16.f32 " \
        "{%0,%1,%2,%3}, {%4,%5,%6,%7}, {%8,%9}, {%0,%1,%2,%3};" \
        : "+f"((D)[0]), "+f"((D)[1]), "+f"((D)[2]), "+f"((D)[3]) \
        : "r"((A)[0]), "r"((A)[1]), "r"((A)[2]), "r"((A)[3]), "r"(B0), "r"(B1))
#define HMMA8(D, A, B0) \
    asm("mma.sync.aligned.m16n8k8.row.col.f32.f16.f16.f32 " \
        "{%0,%1,%2,%3}, {%4,%5}, {%6}, {%0,%1,%2,%3};" \
        : "+f"((D)[0]), "+f"((D)[1]), "+f"((D)[2]), "+f"((D)[3]) \
        : "r"((A)[0]), "r"((A)[1]), "r"(B0))

// MMA for one cell-half (m0 = 0 or 2): d = preactivations for 32 cells x 24 gates
static __device__ __forceinline__ void mma_half(
    float d[2][3][4], int m0, u32 ah_b, u32 ax_b,
    const u32 Bh[3][4][2], const u32 Bx[2]) {
#pragma unroll
    for (int i = 0; i < 2; ++i)
#pragma unroll
        for (int gr = 0; gr < 3; ++gr)
#pragma unroll
            for (int q = 0; q < 4; ++q) d[i][gr][q] = 0.f;
#pragma unroll
    for (int c = 0; c < 4; ++c) {
        u32 a[2][4];
#pragma unroll
        for (int i = 0; i < 2; ++i)
            LDSM4(a[i], ah_b + (u32)((m0 + i) * 2304 + c * 32));
#pragma unroll
        for (int i = 0; i < 2; ++i) {
            HMMA16(d[i][0], a[i], Bh[0][c][0], Bh[0][c][1]);
            HMMA16(d[i][1], a[i], Bh[1][c][0], Bh[1][c][1]);
            HMMA16(d[i][2], a[i], Bh[2][c][0], Bh[2][c][1]);
        }
    }
#pragma unroll
    for (int i = 0; i < 2; ++i) {
        u32 ax[2];
        LDSM2(ax, ax_b + (u32)((m0 + i) * 256));
        HMMA8(d[i][0], ax, Bx[0]);
        HMMA8(d[i][1], ax, Bx[1]);
    }
}

// Epilogue for one cell-half: gates, h update, y partials
static __device__ __forceinline__ void epi_half(
    float d[2][3][4], int m0, int g, int c4, int k0, int wid,
    u16* h16, const float2* ptc, float* yb, float* hreg,
    float wp0, float wt0, float wp1, float wt1, float bb0, float bb1,
    float bn0, float bn1, float ow0, float ow1) {
#pragma unroll
    for (int i = 0; i < 2; ++i) {
#pragma unroll
        for (int hf = 0; hf < 2; ++hf) {
            const int cell = (m0 + i) * 16 + g + hf * 8;
            const int u = (m0 + i) * 4 + hf * 2;
            float2 xv = ptc[cell];
            float Dr0 = d[i][0][2 * hf], Dr1 = d[i][0][2 * hf + 1];
            float Dz0 = d[i][1][2 * hf], Dz1 = d[i][1][2 * hf + 1];
            float Dn0 = d[i][2][2 * hf], Dn1 = d[i][2][2 * hf + 1];
            float2 rr = sigm2_fast(Dr0, Dr1);
            float2 zz = sigm2_fast(Dz0, Dz1);
            float ig0 = fmaf(wp0, xv.x, fmaf(wt0, xv.y, bb0));
            float ig1 = fmaf(wp1, xv.x, fmaf(wt1, xv.y, bb1));
            float n0 = tanha(fmaf(rr.x, Dn0 + bn0, ig0));
            float n1 = tanha(fmaf(rr.y, Dn1 + bn1, ig1));
            float h0 = fmaf(zz.x, hreg[u] - n0, n0);
            float h1 = fmaf(zz.y, hreg[u + 1] - n1, n1);
            hreg[u] = h0; hreg[u + 1] = h1;
            *(u32*)&h16[cell * 72 + k0] = pk(f2h(h0), f2h(h1));
            float yq = fmaf(ow0, h0, ow1 * h1);
            yq += __shfl_xor_sync(0xffffffffu, yq, 1);
            yq += __shfl_xor_sync(0xffffffffu, yq, 2);
            if (c4 == 0) yb[wid * CPB + cell] = yq;
        }
    }
}

__global__ void __launch_bounds__(256, 2)
gru_f16_kernel(const float* __restrict__ precip, const float* __restrict__ temp,
               const float* __restrict__ w_ih, const float* __restrict__ w_hh,
               const float* __restrict__ bias, const float* __restrict__ bias_n,
               const float* __restrict__ out_w, const float* __restrict__ out_b,
               const float* __restrict__ init_h, float* __restrict__ out) {
    extern __shared__ char sm[];
    const u32 sb = s2u(sm);
    u16*  h16  = (u16*)(sm + H16);
    float2* ptb = (float2*)(sm + PTB);
    float* ybuf = (float*)(sm + YPT);

    const int tid  = threadIdx.x;
    const int wid  = tid >> 5;
    const int lane = tid & 31;
    const int g    = lane >> 2;
    const int c4   = lane & 3;
    const int k0   = 8 * wid + 2 * c4;
    const int cellbase = blockIdx.x * CPB;

    // ---- W_hh register fragments (rounded f16) ----
    u32 Bh[3][4][2];
#pragma unroll
    for (int grp = 0; grp < 3; ++grp) {
        const float* wr = w_hh + (grp * 64 + 8 * wid + g) * 64;
#pragma unroll
        for (int c = 0; c < 4; ++c)
#pragma unroll
            for (int rr = 0; rr < 2; ++rr) {
                int kk = c * 16 + rr * 8 + 2 * c4;
                Bh[grp][c][rr] = pk(f2h(wr[kk]), f2h(wr[kk + 1]));
            }
    }
    // ---- x-chunk B frags (r,z gates) ----
    u32 Bx[2];
#pragma unroll
    for (int grp = 0; grp < 2; ++grp) {
        int gate = grp * 64 + 8 * wid + g;
        u32 v = 0;
        if (c4 == 0)      v = pk(f2h(w_ih[gate * 2]), f2h(w_ih[gate * 2 + 1]));
        else if (c4 == 1) v = pk(f2h(bias[gate]), 0);
        Bx[grp] = v;
    }
    // ---- exact scalars for candidate gate + output ----
    const float wp0 = w_ih[(128 + k0) * 2],     wt0 = w_ih[(128 + k0) * 2 + 1];
    const float wp1 = w_ih[(128 + k0 + 1) * 2], wt1 = w_ih[(128 + k0 + 1) * 2 + 1];
    const float bb0 = bias[128 + k0], bb1 = bias[128 + k0 + 1];
    const float bn0 = bias_n[k0],     bn1 = bias_n[k0 + 1];
    const float ow0 = out_w[k0],      ow1 = out_w[k0 + 1];
    const float ob  = out_b[0];

    // ---- h state: fp32 in regs ----
    float hreg[16];
#pragma unroll
    for (int u = 0; u < 16; ++u) hreg[u] = init_h[k0 + (u & 1)];
    for (int idx = tid; idx < 64 * 64; idx += 256)
        h16[(idx >> 6) * 72 + (idx & 63)] = f2h(init_h[idx & 63]);
    // x buf 0 (t=0), pt buf 0; prefetch t=1
    float pv = 0.f, tv = 0.f;
    if (tid < CPB) {
        float p0 = precip[cellbase + tid], t0 = temp[cellbase + tid];
        *(uint4*)(sm + X16 + tid * 16) =
            make_uint4(pk(f2h(p0), f2h(t0)), pk(0x3C00, 0), 0, 0);
        ptb[tid] = make_float2(p0, t0);
        pv = precip[NCELL + cellbase + tid];
        tv = temp[NCELL + cellbase + tid];
    }
    __syncthreads();

    const u32 ah_b    = sb + H16 + (u32)((lane & 15) * 144 + (lane >> 4) * 16);
    const u32 ax_base = sb + X16 + (u32)((lane & 15) * 16);

    float d0[2][3][4], d1[2][3][4];
    // prologue: MMA half0 for t=0
    mma_half(d0, 0, ah_b, ax_base, Bh, Bx);

    for (int t = 0; t < TST; ++t) {
        // ================= phase A =================
        // stage x(t+1), pt(t+1); prefetch x(t+2)
        if (tid < CPB) {
            *(uint4*)(sm + X16 + ((t + 1) & 1) * 1024 + tid * 16) =
                make_uint4(pk(f2h(pv), f2h(tv)), pk(0x3C00, 0), 0, 0);
            ptb[((t + 1) & 1) * CPB + tid] = make_float2(pv, tv);
            int tn = (t + 2 < TST) ? t + 2 : TST - 1;
            pv = precip[tn * NCELL + cellbase + tid];
            tv = temp[tn * NCELL + cellbase + tid];
            // reduce y of step t-1
            if (t > 0) {
                float y = ob;
                const float* yb = ybuf + ((t - 1) & 1) * 512;
#pragma unroll
                for (int w = 0; w < 8; ++w) y += yb[w * CPB + tid];
                out[(t - 1) * NCELL + cellbase + tid] = y;
            }
        }
        // MMA(half1, t) + EPI(half0, t) — independent, overlap pipes
        mma_half(d1, 2, ah_b, ax_base + (u32)((t & 1) * 1024), Bh, Bx);
        epi_half(d0, 0, g, c4, k0, wid, h16, ptb + (t & 1) * CPB,
                 ybuf + (t & 1) * 512, hreg,
                 wp0, wt0, wp1, wt1, bb0, bb1, bn0, bn1, ow0, ow1);
        __syncthreads();

        // ================= phase B =================
        // MMA(half0, t+1) + EPI(half1, t)
        if (t + 1 < TST)
            mma_half(d0, 0, ah_b, ax_base + (u32)(((t + 1) & 1) * 1024), Bh, Bx);
        epi_half(d1, 2, g, c4, k0, wid, h16, ptb + (t & 1) * CPB,
                 ybuf + (t & 1) * 512, hreg,
                 wp0, wt0, wp1, wt1, bb0, bb1, bn0, bn1, ow0, ow1);
        __syncthreads();
    }

    // trailing y reduce for t = TST-1
    if (tid < CPB) {
        float y = ob;
        const float* yb = ybuf + ((TST - 1) & 1) * 512;
#pragma unroll
        for (int w = 0; w < 8; ++w) y += yb[w * CPB + tid];
        out[(TST - 1) * NCELL + cellbase + tid] = y;
    }

    // ---- final hidden state (exact fp32 from regs) ----
#pragma unroll
    for (int u = 0; u < 16; ++u) {
        int cell = (u >> 2) * 16 + g + ((u >> 1) & 1) * 8;
        int k = k0 + (u & 1);
        out[(long long)TST * NCELL + (long long)(cellbase + cell) * 64 + k] = hreg[u];
    }
}

extern "C" void kernel_launch(void* const* d_in, const int* in_sizes, int n_in,
                              void* d_out, int out_size) {
    const float* precip = (const float*)d_in[0];
    const float* temp   = (const float*)d_in[1];
    const float* w_ih   = (const float*)d_in[2];
    const float* w_hh   = (const float*)d_in[3];
    const float* bias   = (const float*)d_in[4];
    const float* bias_n = (const float*)d_in[5];
    const float* out_w  = (const float*)d_in[6];
    const float* out_b  = (const float*)d_in[7];
    const float* init_h = (const float*)d_in[8];
    float* out = (float*)d_out;

    gru_f16_kernel<<<NBLK, 256, SMB>>>(
        precip, temp, w_ih, w_hh, bias, bias_n, out_w, out_b, init_h, out);
}

// round 13
// speedup vs baseline: 3.2270x; 1.0086x over previous
#include <cuda_runtime.h>
#include <cuda_fp16.h>
#include <cstdint>

#define NCELL 65536
#define TST   365
#define CPB   64
#define NBLK  (NCELL / CPB)

// smem byte offsets
#define H16   0        // h f16 tile: 2 bufs x 64 rows x 144B   = 18432
#define X16   18432    // x f16 tile: 2 bufs x 64 rows x 16B    =  2048
#define PTB   20480    // p,t fp32:   2 bufs x 64 x float2      =  1024
#define YPT   21504    // y partials: 2 bufs x 8 x 64 f32       =  4096
#define SMB   25600

typedef unsigned int u32;
typedef unsigned short u16;

static __device__ __forceinline__ u32 s2u(const void* p) {
    u32 a;
    asm("{ .reg .u64 t; cvta.to.shared.u64 t, %1; cvt.u32.u64 %0, t; }"
        : "=r"(a) : "l"(p));
    return a;
}
static __device__ __forceinline__ u16 f2h(float f) {
    return __half_as_ushort(__float2half(f));
}
static __device__ __forceinline__ u32 pk(u16 a, u16 b) {
    return (u32)a | ((u32)b << 16);
}
static __device__ __forceinline__ float tanha(float x) {
    float r;
    asm("tanh.approx.f32 %0, %1;" : "=f"(r) : "f"(x));
    return r;
}
// packed sigmoid of two fp32 pre-activations via one f16x2 tanh MUFU
static __device__ __forceinline__ float2 sigm2_fast(float x0, float x1) {
    u32 p, s, th;
    asm("cvt.rn.f16x2.f32 %0, %1, %2;" : "=r"(p) : "f"(x1), "f"(x0)); // lo=x0,hi=x1
    asm("mul.f16x2 %0, %1, %2;" : "=r"(s) : "r"(p), "r"(0x38003800u)); // * 0.5
    asm("tanh.approx.f16x2 %0, %1;" : "=r"(th) : "r"(s));
    __half2 h2 = *reinterpret_cast<__half2*>(&th);
    float2 f = __half22float2(h2);
    return make_float2(fmaf(f.x, 0.5f, 0.5f), fmaf(f.y, 0.5f, 0.5f));
}

#define LDSM4(R, ad) \
    asm volatile("ldmatrix.sync.aligned.m8n8.x4.shared.b16 {%0,%1,%2,%3}, [%4];" \
        : "=r"((R)[0]), "=r"((R)[1]), "=r"((R)[2]), "=r"((R)[3]) : "r"(ad) : "memory")
#define LDSM2(R, ad) \
    asm volatile("ldmatrix.sync.aligned.m8n8.x2.shared.b16 {%0,%1}, [%2];" \
        : "=r"((R)[0]), "=r"((R)[1]) : "r"(ad) : "memory")
#define HMMA16(D, A, B0, B1) \
    asm("mma.sync.aligned.m16n8k16.row.col.f32.f16.f16.f32 " \
        "{%0,%1,%2,%3}, {%4,%5,%6,%7}, {%8,%9}, {%0,%1,%2,%3};" \
        : "+f"((D)[0]), "+f"((D)[1]), "+f"((D)[2]), "+f"((D)[3]) \
        : "r"((A)[0]), "r"((A)[1]), "r"((A)[2]), "r"((A)[3]), "r"(B0), "r"(B1))
#define HMMA8(D, A, B0) \
    asm("mma.sync.aligned.m16n8k8.row.col.f32.f16.f16.f32 " \
        "{%0,%1,%2,%3}, {%4,%5}, {%6}, {%0,%1,%2,%3};" \
        : "+f"((D)[0]), "+f"((D)[1]), "+f"((D)[2]), "+f"((D)[3]) \
        : "r"((A)[0]), "r"((A)[1]), "r"(B0))

__global__ void __launch_bounds__(256, 2)
gru_f16_kernel(const float* __restrict__ precip, const float* __restrict__ temp,
               const float* __restrict__ w_ih, const float* __restrict__ w_hh,
               const float* __restrict__ bias, const float* __restrict__ bias_n,
               const float* __restrict__ out_w, const float* __restrict__ out_b,
               const float* __restrict__ init_h, float* __restrict__ out) {
    extern __shared__ char sm[];
    const u32 sb = s2u(sm);
    u16*  h16  = (u16*)(sm + H16);           // two 4608-u16 buffers
    float2* ptb = (float2*)(sm + PTB);
    float* ybuf = (float*)(sm + YPT);

    const int tid  = threadIdx.x;
    const int wid  = tid >> 5;
    const int lane = tid & 31;
    const int g    = lane >> 2;
    const int c4   = lane & 3;
    const int k0   = 8 * wid + 2 * c4;
    const int cellbase = blockIdx.x * CPB;

    // ---- W_hh register fragments (rounded f16) ----
    u32 Bh[3][4][2];
#pragma unroll
    for (int grp = 0; grp < 3; ++grp) {
        const float* wr = w_hh + (grp * 64 + 8 * wid + g) * 64;
#pragma unroll
        for (int c = 0; c < 4; ++c)
#pragma unroll
            for (int rr = 0; rr < 2; ++rr) {
                int kk = c * 16 + rr * 8 + 2 * c4;
                Bh[grp][c][rr] = pk(f2h(wr[kk]), f2h(wr[kk + 1]));
            }
    }
    // ---- x-chunk B frags: r,z carry (w_p,w_t | bias); n carries (0 | bias_n) ----
    // A x-rows per cell: (p, t, 1, 0, 0, 0, 0, 0)
    u32 Bx[3];
#pragma unroll
    for (int grp = 0; grp < 2; ++grp) {
        int gate = grp * 64 + 8 * wid + g;
        u32 v = 0;
        if (c4 == 0)      v = pk(f2h(w_ih[gate * 2]), f2h(w_ih[gate * 2 + 1]));
        else if (c4 == 1) v = pk(f2h(bias[gate]), 0);
        Bx[grp] = v;
    }
    {
        u32 v = 0;
        if (c4 == 1) v = pk(f2h(bias_n[8 * wid + g]), 0);   // bn * 1.0 row
        Bx[2] = v;
    }
    // ---- exact scalars for candidate gate + output ----
    const float wp0 = w_ih[(128 + k0) * 2],     wt0 = w_ih[(128 + k0) * 2 + 1];
    const float wp1 = w_ih[(128 + k0 + 1) * 2], wt1 = w_ih[(128 + k0 + 1) * 2 + 1];
    const float bb0 = bias[128 + k0], bb1 = bias[128 + k0 + 1];
    const float ow0 = out_w[k0],      ow1 = out_w[k0 + 1];
    const float ob  = out_b[0];

    // ---- h state: fp32 in regs (thread owns fixed (cell,k) pairs) ----
    float hreg[16];
#pragma unroll
    for (int u = 0; u < 16; ++u) hreg[u] = init_h[k0 + (u & 1)];
    // h buffer 0 init
    for (int idx = tid; idx < 64 * 64; idx += 256)
        h16[(idx >> 6) * 72 + (idx & 63)] = f2h(init_h[idx & 63]);
    // x buf 0 (t=0) + pt buf 0; prefetch t=1
    float pv = 0.f, tv = 0.f;
    if (tid < CPB) {
        float p0 = precip[cellbase + tid], t0 = temp[cellbase + tid];
        *(uint4*)(sm + X16 + tid * 16) =
            make_uint4(pk(f2h(p0), f2h(t0)), pk(0x3C00, 0), 0, 0);  // 1.0h
        ptb[tid] = make_float2(p0, t0);
        pv = precip[NCELL + cellbase + tid];
        tv = temp[NCELL + cellbase + tid];
    }
    __syncthreads();

    const u32 ah_lm = sb + H16 + (u32)((lane & 15) * 144 + (lane >> 4) * 16);
    const u32 ax_lm = sb + X16 + (u32)((lane & 15) * 16);

    for (int t = 0; t < TST; ++t) {
        const int pr = t & 1, nx = (t + 1) & 1;
        float d[4][3][4];
#pragma unroll
        for (int mt = 0; mt < 4; ++mt)
#pragma unroll
            for (int gr = 0; gr < 3; ++gr)
#pragma unroll
                for (int q = 0; q < 4; ++q) d[mt][gr][q] = 0.f;

        // ---- MMA: reads hbuf[pr], xbuf[pr] ----
        const u32 ah_b = ah_lm + (u32)(pr * 9216);
        const u32 ax_b = ax_lm + (u32)(pr * 1024);
#pragma unroll
        for (int c = 0; c < 4; ++c) {
            u32 a[4][4];
#pragma unroll
            for (int mt = 0; mt < 4; ++mt)
                LDSM4(a[mt], ah_b + mt * 2304 + c * 32);
#pragma unroll
            for (int mt = 0; mt < 4; ++mt) {
                HMMA16(d[mt][0], a[mt], Bh[0][c][0], Bh[0][c][1]);
                HMMA16(d[mt][1], a[mt], Bh[1][c][0], Bh[1][c][1]);
                HMMA16(d[mt][2], a[mt], Bh[2][c][0], Bh[2][c][1]);
            }
        }
#pragma unroll
        for (int mt = 0; mt < 4; ++mt) {
            u32 ax[2];
            LDSM2(ax, ax_b + mt * 256);
            HMMA8(d[mt][0], ax, Bx[0]);
            HMMA8(d[mt][1], ax, Bx[1]);
            HMMA8(d[mt][2], ax, Bx[2]);       // adds bias_n to candidate pre-act
        }

        // ---- staging warps: x(t+1), pt(t+1), y-reduce(t-1), prefetch(t+2) ----
        if (tid < CPB) {
            *(uint4*)(sm + X16 + nx * 1024 + tid * 16) =
                make_uint4(pk(f2h(pv), f2h(tv)), pk(0x3C00, 0), 0, 0);
            ptb[nx * CPB + tid] = make_float2(pv, tv);
            int tn = (t + 2 < TST) ? t + 2 : TST - 1;
            pv = precip[tn * NCELL + cellbase + tid];
            tv = temp[tn * NCELL + cellbase + tid];
            if (t > 0) {
                float y = ob;
                const float* yb = ybuf + ((t - 1) & 1) * 512;
#pragma unroll
                for (int w = 0; w < 8; ++w) y += yb[w * CPB + tid];
                out[(t - 1) * NCELL + cellbase + tid] = y;
            }
        }

        // ---- epilogue: writes hbuf[nx] (disjoint from MMA reads), ybuf[pr] ----
        u16* h16w = h16 + nx * 4608;
        const float2* ptc = ptb + pr * CPB;
        float* yb = ybuf + pr * 512;
#pragma unroll
        for (int mt = 0; mt < 4; ++mt) {
#pragma unroll
            for (int hf = 0; hf < 2; ++hf) {
                const int cell = mt * 16 + g + hf * 8;
                const int u = mt * 4 + hf * 2;
                float2 xv = ptc[cell];
                float Dr0 = d[mt][0][2 * hf], Dr1 = d[mt][0][2 * hf + 1];
                float Dz0 = d[mt][1][2 * hf], Dz1 = d[mt][1][2 * hf + 1];
                float Dn0 = d[mt][2][2 * hf], Dn1 = d[mt][2][2 * hf + 1];
                float2 rr = sigm2_fast(Dr0, Dr1);
                float2 zz = sigm2_fast(Dz0, Dz1);
                float ig0 = fmaf(wp0, xv.x, fmaf(wt0, xv.y, bb0));
                float ig1 = fmaf(wp1, xv.x, fmaf(wt1, xv.y, bb1));
                float n0 = tanha(fmaf(rr.x, Dn0, ig0));   // bn already in Dn
                float n1 = tanha(fmaf(rr.y, Dn1, ig1));
                float h0 = fmaf(zz.x, hreg[u] - n0, n0);
                float h1 = fmaf(zz.y, hreg[u + 1] - n1, n1);
                hreg[u] = h0; hreg[u + 1] = h1;
                *(u32*)&h16w[cell * 72 + k0] = pk(f2h(h0), f2h(h1));
                float yq = fmaf(ow0, h0, ow1 * h1);
                yq += __shfl_xor_sync(0xffffffffu, yq, 1);
                yq += __shfl_xor_sync(0xffffffffu, yq, 2);
                if (c4 == 0) yb[wid * CPB + cell] = yq;
            }
        }
        __syncthreads();   // single barrier per step
    }

    // trailing y reduce for t = TST-1
    if (tid < CPB) {
        float y = ob;
        const float* yb = ybuf + ((TST - 1) & 1) * 512;
#pragma unroll
        for (int w = 0; w < 8; ++w) y += yb[w * CPB + tid];
        out[(TST - 1) * NCELL + cellbase + tid] = y;
    }

    // ---- final hidden state (exact fp32 from regs) ----
#pragma unroll
    for (int u = 0; u < 16; ++u) {
        int cell = (u >> 2) * 16 + g + ((u >> 1) & 1) * 8;
        int k = k0 + (u & 1);
        out[(long long)TST * NCELL + (long long)(cellbase + cell) * 64 + k] = hreg[u];
    }
}

extern "C" void kernel_launch(void* const* d_in, const int* in_sizes, int n_in,
                              void* d_out, int out_size) {
    const float* precip = (const float*)d_in[0];
    const float* temp   = (const float*)d_in[1];
    const float* w_ih   = (const float*)d_in[2];
    const float* w_hh   = (const float*)d_in[3];
    const float* bias   = (const float*)d_in[4];
    const float* bias_n = (const float*)d_in[5];
    const float* out_w  = (const float*)d_in[6];
    const float* out_b  = (const float*)d_in[7];
    const float* init_h = (const float*)d_in[8];
    float* out = (float*)d_out;

    gru_f16_kernel<<<NBLK, 256, SMB>>>(
        precip, temp, w_ih, w_hh, bias, bias_n, out_w, out_b, init_h, out);
}